// round 1
// baseline (speedup 1.0000x reference)
#include <cuda_runtime.h>

#define N_NODES 16384
#define N_EDGES 262144

// Scratch (static device globals — no allocation at runtime)
__device__ float g_up[N_NODES * 128];    // per node: [s1(32), v1_x(32), v1_y(32), v1_z(32)]
__device__ float g_acc[N_NODES * 256];   // per node: [S(64), V0(64), V1(64), V2(64)]

__device__ __forceinline__ float silu_f(float x) {
    return x / (1.0f + __expf(-x));
}

// ---------------------------------------------------------------------------
// Kernel 0: zero the accumulator (16 MB)
// ---------------------------------------------------------------------------
__global__ void zero_acc_kernel() {
    int i = blockIdx.x * blockDim.x + threadIdx.x;   // 4096*256 = 1,048,576 float4
    ((float4*)g_acc)[i] = make_float4(0.f, 0.f, 0.f, 0.f);
}

// ---------------------------------------------------------------------------
// Kernel 1: node up-projection  s1 = s@W_up_s * 32^-0.5,  v1 = v@W_up_v * 32^-0.5
// block = 128 threads, one node per iteration
// ---------------------------------------------------------------------------
__global__ void up_kernel(const float* __restrict__ nf,
                          const float* __restrict__ Wus,
                          const float* __restrict__ Wuv) {
    __shared__ float sWs[1024];
    __shared__ float sWv[1024];
    __shared__ float sIn[128];
    int t = threadIdx.x;
    for (int i = t; i < 1024; i += 128) { sWs[i] = Wus[i]; sWv[i] = Wuv[i]; }
    __syncthreads();
    int k = t & 31, sec = t >> 5;
    for (int n = blockIdx.x; n < N_NODES; n += gridDim.x) {
        sIn[t] = nf[n * 128 + t];
        __syncthreads();
        float acc = 0.f;
        if (sec == 0) {
            #pragma unroll 8
            for (int m = 0; m < 32; m++) acc = fmaf(sIn[m], sWs[m * 32 + k], acc);
        } else {
            int i = sec - 1;
            #pragma unroll 8
            for (int m = 0; m < 32; m++) acc = fmaf(sIn[32 + m * 3 + i], sWv[m * 32 + k], acc);
        }
        g_up[(size_t)n * 128 + t] = acc * 0.17677669529663687f;  // 32^-0.5
        __syncthreads();
    }
}

// ---------------------------------------------------------------------------
// Kernel 2: edge kernel. One warp per edge:
//   radial MLP (8->8 silu ->128), gather sender up-features, build 256-float
//   message in SMEM, flush with vectorized red.global.add.v4.f32
// ---------------------------------------------------------------------------
__global__ void edge_kernel(const float* __restrict__ edge_sh,
                            const float* __restrict__ radial,
                            const float* __restrict__ W_r1,
                            const float* __restrict__ W_r2,
                            const int* __restrict__ senders,
                            const int* __restrict__ receivers) {
    __shared__ float sW1[64];
    __shared__ float sW2[1024];
    __shared__ __align__(16) float smsg[8][256];
    int t = threadIdx.x;
    if (t < 64) sW1[t] = W_r1[t];
    for (int i = t; i < 1024; i += 256) sW2[i] = W_r2[i];
    __syncthreads();

    int warp = t >> 5, lane = t & 31;
    int j8 = lane & 7;
    float* msg = smsg[warp];
    const float INV_SQRT8 = 0.3535533905932738f;
    const float SC = INV_SQRT8 * 0.25f;   // fold radial scale * AVG_NEIGH^-0.5

    for (int e = blockIdx.x * 8 + warp; e < N_EDGES; e += gridDim.x * 8) {
        int snd = senders[e];
        int rcv = receivers[e];

        // radial MLP: lanes 0..7 hold r; every lane computes h for j = lane&7
        float r = (lane < 8) ? radial[e * 8 + lane] : 0.f;
        float pre = 0.f;
        #pragma unroll
        for (int k = 0; k < 8; k++) {
            float rk = __shfl_sync(0xffffffffu, r, k);
            pre = fmaf(rk, sW1[k * 8 + j8], pre);
        }
        float h = silu_f(pre * INV_SQRT8);

        // w = h @ W_r2 : lane m computes w_ss, w_vs, w_vt, w_st for mul m
        float w0 = 0.f, w1 = 0.f, w2 = 0.f, w3 = 0.f;
        #pragma unroll
        for (int j = 0; j < 8; j++) {
            float hj = __shfl_sync(0xffffffffu, h, j);
            w0 = fmaf(hj, sW2[j * 128 + lane], w0);
            w1 = fmaf(hj, sW2[j * 128 + 32 + lane], w1);
            w2 = fmaf(hj, sW2[j * 128 + 64 + lane], w2);
            w3 = fmaf(hj, sW2[j * 128 + 96 + lane], w3);
        }
        w0 *= SC; w1 *= SC; w2 *= SC; w3 *= SC;

        // gather sender up-features (L2-resident)
        const float* up = g_up + (size_t)snd * 128;
        float ss  = up[lane];
        float vs0 = up[32 + lane];
        float vs1 = up[64 + lane];
        float vs2 = up[96 + lane];
        float y0 = edge_sh[e * 4 + 1];
        float y1 = edge_sh[e * 4 + 2];
        float y2 = edge_sh[e * 4 + 3];

        float dot = (vs0 * y0 + vs1 * y1 + vs2 * y2) * 0.5773502691896258f;
        float sst = ss * w2;

        msg[lane]        = ss  * w0;   // S ss-half
        msg[32 + lane]   = dot * w3;   // S st-half
        msg[64 + lane]   = vs0 * w1;   msg[96  + lane] = sst * y0;  // V0
        msg[128 + lane]  = vs1 * w1;   msg[160 + lane] = sst * y1;  // V1
        msg[192 + lane]  = vs2 * w1;   msg[224 + lane] = sst * y2;  // V2
        __syncwarp();

        float* dst = g_acc + (size_t)rcv * 256;
        #pragma unroll
        for (int q = 0; q < 2; q++) {
            float4 v = ((const float4*)msg)[q * 32 + lane];
            asm volatile("red.global.add.v4.f32 [%0], {%1,%2,%3,%4};"
                         :: "l"(dst + (q * 32 + lane) * 4),
                            "f"(v.x), "f"(v.y), "f"(v.z), "f"(v.w)
                         : "memory");
        }
        __syncwarp();   // msg reuse next iteration
    }
}

// ---------------------------------------------------------------------------
// Kernel 3: node down-projection + species skip + gating. One warp per node.
// ---------------------------------------------------------------------------
__global__ void down_kernel(const float* __restrict__ nf,
                            const float* __restrict__ W_dn_s,
                            const float* __restrict__ W_dn_v,
                            const float* __restrict__ W_sk_s,
                            const float* __restrict__ W_sk_v,
                            const int* __restrict__ species,
                            float* __restrict__ out) {
    __shared__ float sWs[64 * 64];
    __shared__ float sWv[64 * 32];
    __shared__ __align__(16) float sStage[8][384];
    int t = threadIdx.x;
    for (int i = t; i < 4096; i += 256) sWs[i] = W_dn_s[i];
    for (int i = t; i < 2048; i += 256) sWv[i] = W_dn_v[i];
    __syncthreads();

    int warp = t >> 5, lane = t & 31;
    int n = blockIdx.x * 8 + warp;
    float* st = sStage[warp];
    const float* acc = g_acc + (size_t)n * 256;
    const float* nfp = nf + (size_t)n * 128;
    for (int i = lane; i < 256; i += 32) st[i] = acc[i];
    for (int i = lane; i < 128; i += 32) st[256 + i] = nfp[i];
    __syncwarp();

    int spec = species[n];
    const float* Ws = W_sk_s + spec * 2048;   // (32,64)
    const float* Wv = W_sk_v + spec * 1024;   // (32,32)

    float gs0 = 0.f, gs1 = 0.f, gv0 = 0.f, gv1 = 0.f, gv2 = 0.f;
    #pragma unroll 8
    for (int m = 0; m < 64; m++) {
        float Sm = st[m];
        float V0 = st[64 + m], V1 = st[128 + m], V2 = st[192 + m];
        float a = sWs[m * 64 + lane];
        float b = sWs[m * 64 + 32 + lane];
        float c = sWv[m * 32 + lane];
        gs0 = fmaf(Sm, a, gs0); gs1 = fmaf(Sm, b, gs1);
        gv0 = fmaf(V0, c, gv0); gv1 = fmaf(V1, c, gv1); gv2 = fmaf(V2, c, gv2);
    }

    float sk0 = 0.f, sk1 = 0.f, sv0 = 0.f, sv1 = 0.f, sv2 = 0.f;
    #pragma unroll 8
    for (int m = 0; m < 32; m++) {
        float sm = st[256 + m];
        float v0 = st[288 + m * 3 + 0];
        float v1 = st[288 + m * 3 + 1];
        float v2 = st[288 + m * 3 + 2];
        float a = Ws[m * 64 + lane];
        float b = Ws[m * 64 + 32 + lane];
        float c = Wv[m * 32 + lane];
        sk0 = fmaf(sm, a, sk0); sk1 = fmaf(sm, b, sk1);
        sv0 = fmaf(v0, c, sv0); sv1 = fmaf(v1, c, sv1); sv2 = fmaf(v2, c, sv2);
    }

    const float A = 0.5f * 0.125f;                 // 0.5 * (2*MUL)^-0.5
    const float B = 0.5f * 0.17677669529663687f;   // 0.5 * MUL^-0.5
    float G0 = gs0 * A + sk0 * B;
    float G1 = gs1 * A + sk1 * B;
    float H0 = gv0 * A + sv0 * B;
    float H1 = gv1 * A + sv1 * B;
    float H2 = gv2 * A + sv2 * B;

    float feat = silu_f(G0);
    float gate = silu_f(G1);

    float* o = out + (size_t)n * 128;
    o[lane] = feat;
    o[32 + lane * 3 + 0] = H0 * gate;
    o[32 + lane * 3 + 1] = H1 * gate;
    o[32 + lane * 3 + 2] = H2 * gate;
}

// ---------------------------------------------------------------------------
extern "C" void kernel_launch(void* const* d_in, const int* in_sizes, int n_in,
                              void* d_out, int out_size) {
    const float* nf  = (const float*)d_in[0];
    const float* esh = (const float*)d_in[1];
    const float* rad = (const float*)d_in[2];
    const float* Wus = (const float*)d_in[3];
    const float* Wuv = (const float*)d_in[4];
    const float* Wr1 = (const float*)d_in[5];
    const float* Wr2 = (const float*)d_in[6];
    const float* Wds = (const float*)d_in[7];
    const float* Wdv = (const float*)d_in[8];
    const float* Wss = (const float*)d_in[9];
    const float* Wsv = (const float*)d_in[10];
    const int* snd  = (const int*)d_in[11];
    const int* rcv  = (const int*)d_in[12];
    const int* spec = (const int*)d_in[13];
    float* out = (float*)d_out;

    zero_acc_kernel<<<4096, 256>>>();
    up_kernel<<<2048, 128>>>(nf, Wus, Wuv);
    edge_kernel<<<8192, 256>>>(esh, rad, Wr1, Wr2, snd, rcv);
    down_kernel<<<2048, 256>>>(nf, Wds, Wdv, Wss, Wsv, spec, out);
}